// round 3
// baseline (speedup 1.0000x reference)
#include <cuda_runtime.h>
#include <cuda_bf16.h>
#include <cstdint>

// Problem constants
#define B_  128
#define D_  128
#define T_  2048
#define C_  64
#define N_  (B_ * T_)        // 262144 rows
#define ND_ ((long long)N_ * D_)

// Tiling
#define DG      16           // d's per block
#define TSPLIT  2            // split T for more blocks
#define NBLK    (B_ * (D_ / DG) * TSPLIT)   // 2048 blocks
#define THREADS 256

// Device scratch (no allocations allowed)
__device__ float g_featsum[C_ * D_];   // [C][D]
__device__ int   g_counts[C_];
__device__ float g_sumsq;
__device__ int   g_lab64;              // 1 if labels are int64, 0 if int32

// ---------------------------------------------------------------------------
// Kernel 0: zero scratch + detect label dtype (int64 vs int32) device-side.
// If labels are int64 (values in [0,64)), every 64-bit word is < 64.
// If they are int32, pairs interpreted as int64 are huge with prob ~1-1/64.
// ---------------------------------------------------------------------------
__global__ void cl_init_kernel(const void* __restrict__ label_raw) {
    int idx = blockIdx.x * blockDim.x + threadIdx.x;
    if (idx < C_ * D_) g_featsum[idx] = 0.0f;
    if (idx < C_)      g_counts[idx]  = 0;
    if (idx == 0) {
        g_sumsq = 0.0f;
        const long long* l = (const long long*)label_raw;
        int ok = 1;
        #pragma unroll 4
        for (int i = 0; i < 64; i++) {
            long long v = l[i];
            if (v < 0 || v >= C_) { ok = 0; break; }
        }
        g_lab64 = ok;
    }
}

// ---------------------------------------------------------------------------
// Kernel 1: streaming pass.
// Block = (b, d-group of DG, t-chunk). Coalesced feature loads along t.
// Per-block shared histogram bins s_acc[DG][C], merged once to global.
// Also accumulates sum(feat^2) and (for dgrp==0 blocks) the label histogram.
// ---------------------------------------------------------------------------
__global__ void __launch_bounds__(THREADS)
cl_main_kernel(const float* __restrict__ feature,
               const void* __restrict__ label_raw) {
    const int bid    = blockIdx.x;
    const int tchunk = bid % TSPLIT;
    const int dgrp   = (bid / TSPLIT) % (D_ / DG);
    const int b      = bid / (TSPLIT * (D_ / DG));
    const int d0     = dgrp * DG;

    __shared__ float s_acc[DG * C_];
    __shared__ int   s_cnt[C_];
    __shared__ float s_warp[THREADS / 32];

    const bool do_cnt = (dgrp == 0);

    for (int i = threadIdx.x; i < DG * C_; i += THREADS) s_acc[i] = 0.0f;
    if (do_cnt) {
        for (int i = threadIdx.x; i < C_; i += THREADS) s_cnt[i] = 0;
    }
    __syncthreads();

    const int lab64 = g_lab64;
    const int* __restrict__ lab32 = (const int*)label_raw;

    const int t_begin = tchunk * (T_ / TSPLIT);
    const int t_end   = t_begin + (T_ / TSPLIT);

    const float* __restrict__ fbase =
        feature + (size_t)b * (D_ * T_) + (size_t)d0 * T_;
    const int lbase = b * T_;

    float sumsq = 0.0f;

    for (int t = t_begin + threadIdx.x; t < t_end; t += THREADS) {
        const int li  = lbase + t;
        const int lab = lab64 ? lab32[2 * li] : lab32[li];
        if (do_cnt) atomicAdd(&s_cnt[lab], 1);
        #pragma unroll
        for (int dg = 0; dg < DG; dg++) {
            float v = __ldg(&fbase[dg * T_ + t]);
            sumsq += v * v;
            atomicAdd(&s_acc[dg * C_ + lab], v);
        }
    }

    // sumsq: warp shuffle reduce -> one value per warp
    #pragma unroll
    for (int o = 16; o > 0; o >>= 1)
        sumsq += __shfl_down_sync(0xFFFFFFFFu, sumsq, o);
    if ((threadIdx.x & 31) == 0) s_warp[threadIdx.x >> 5] = sumsq;

    __syncthreads();

    if (threadIdx.x == 0) {
        float s = 0.0f;
        #pragma unroll
        for (int i = 0; i < THREADS / 32; i++) s += s_warp[i];
        atomicAdd(&g_sumsq, s);
    }

    // merge shared bins -> global featsum [C][D]
    for (int i = threadIdx.x; i < DG * C_; i += THREADS) {
        const int dg = i / C_;
        const int c  = i - dg * C_;
        const float v = s_acc[i];
        if (v != 0.0f) atomicAdd(&g_featsum[c * D_ + d0 + dg], v);
    }

    if (do_cnt) {
        for (int i = threadIdx.x; i < C_; i += THREADS) {
            const int cv = s_cnt[i];
            if (cv) atomicAdd(&g_counts[i], cv);
        }
    }
}

// ---------------------------------------------------------------------------
// Kernel 2: finalize. Single block.
//   difference[c][d] = count>0 ? centers - featsum/count : 0
//   loss = (sumsq + sum_c cnt*||ctr||^2 - 2*sum centers.featsum) / (N*D)
// Output layout: out[0] = loss, out[1..8192] = difference row-major [C][D].
// ---------------------------------------------------------------------------
__global__ void __launch_bounds__(1024)
cl_finalize_kernel(const float* __restrict__ centers,
                   float* __restrict__ out) {
    __shared__ float s_warp[32];

    float local = 0.0f;
    for (int i = threadIdx.x; i < C_ * D_; i += 1024) {
        const int   c   = i / D_;
        const float ctr = centers[i];
        const float fs  = g_featsum[i];
        const int   cnt = g_counts[c];
        const float diff = (cnt > 0) ? (ctr - fs / (float)cnt) : 0.0f;
        out[1 + i] = diff;
        local += (float)cnt * ctr * ctr - 2.0f * ctr * fs;
    }

    #pragma unroll
    for (int o = 16; o > 0; o >>= 1)
        local += __shfl_down_sync(0xFFFFFFFFu, local, o);
    if ((threadIdx.x & 31) == 0) s_warp[threadIdx.x >> 5] = local;
    __syncthreads();

    if (threadIdx.x == 0) {
        float cross = 0.0f;
        #pragma unroll
        for (int i = 0; i < 32; i++) cross += s_warp[i];
        out[0] = (g_sumsq + cross) / (float)ND_;
    }
}

// ---------------------------------------------------------------------------
extern "C" void kernel_launch(void* const* d_in, const int* in_sizes, int n_in,
                              void* d_out, int out_size) {
    const float* feature = (const float*)d_in[0];
    const void*  label   = d_in[1];
    const float* centers = (const float*)d_in[2];
    float* out = (float*)d_out;

    cl_init_kernel<<<(C_ * D_ + 255) / 256, 256>>>(label);
    cl_main_kernel<<<NBLK, THREADS>>>(feature, label);
    cl_finalize_kernel<<<1, 1024>>>(centers, out);
}

// round 4
// speedup vs baseline: 1.8259x; 1.8259x over previous
#include <cuda_runtime.h>
#include <cstdint>

// Problem constants
#define B_  128
#define D_  128
#define T_  2048
#define C_  64
#define N_  (B_ * T_)                       // 262144
#define ND_ ((long long)N_ * D_)            // 33.5M

// Tiling
#define CHUNK       256                     // t's per chunk
#define NCHUNK_TOT  (T_ / CHUNK)            // 8 chunks per b
#define NCHUNKS_BLK 4                       // chunks per main block
#define TSPLIT      (NCHUNK_TOT / NCHUNKS_BLK)  // 2
#define DG          32                      // d's per main block
#define NDGRP       (D_ / DG)               // 4
#define ST          (CHUNK + 1)             // 257: odd stride -> conflict-free
#define THREADS     256
#define NCU_TOT     (B_ * NCHUNK_TOT)       // 1024 chunk units

// ---------------- device scratch (no allocations allowed) ----------------
__device__ float          g_featsum[C_ * D_];               // [C][D]
__device__ float          g_sumsq;
__device__ unsigned short g_list[NCU_TOT * CHUNK];          // bucketed t-idx
__device__ unsigned short g_base[NCU_TOT * C_];             // excl. prefix
__device__ unsigned short g_cnt [NCU_TOT * C_];             // per-chunk counts

// ---------------------------------------------------------------------------
// K1: bucket t-indices by class per (b, chunk). Also zeroes global scratch.
// Label dtype (int64 vs int32) detected device-side from a safe prefix.
// ---------------------------------------------------------------------------
__global__ void __launch_bounds__(THREADS)
cl_bucket_kernel(const void* __restrict__ label_raw) {
    const int cu  = blockIdx.x;             // 0..1023
    const int b   = cu / NCHUNK_TOT;
    const int tc  = cu % NCHUNK_TOT;
    const int tid = threadIdx.x;

    __shared__ int           s_cnt[C_];
    __shared__ int           s_off[C_];
    __shared__ int           s_lab64;
    __shared__ unsigned char s_lab[CHUNK];

    // distributed zeroing of g_featsum / g_sumsq (blocks 0..31 cover 8192 f32)
    if (cu < (C_ * D_) / THREADS)
        g_featsum[cu * THREADS + tid] = 0.0f;
    if (cu == 0 && tid == 0) g_sumsq = 0.0f;

    if (tid < C_) s_cnt[tid] = 0;

    // dtype detect: first 64 int64 words (512B, always in-bounds)
    if (tid == 0) {
        const long long* l = (const long long*)label_raw;
        int ok = 1;
        for (int i = 0; i < 64; i++) {
            long long v = l[i];
            if (v < 0 || v >= C_) { ok = 0; break; }
        }
        s_lab64 = ok;
    }
    __syncthreads();

    const int* __restrict__ lab32 = (const int*)label_raw;
    const int gi  = b * T_ + tc * CHUNK + tid;
    const int lab = s_lab64 ? lab32[2 * gi] : lab32[gi];
    s_lab[tid] = (unsigned char)lab;
    atomicAdd(&s_cnt[lab], 1);
    __syncthreads();

    // exclusive prefix over 64 counters (serial, cheap)
    if (tid == 0) {
        int run = 0;
        for (int c = 0; c < C_; c++) { s_off[c] = run; run += s_cnt[c]; }
    }
    __syncthreads();

    if (tid < C_) {
        g_base[cu * C_ + tid] = (unsigned short)s_off[tid];
        g_cnt [cu * C_ + tid] = (unsigned short)s_cnt[tid];
    }
    __syncthreads();

    const int pos = atomicAdd(&s_off[s_lab[tid]], 1);
    g_list[cu * CHUNK + pos] = (unsigned short)tid;
}

// ---------------------------------------------------------------------------
// K2: streaming pass. Block = (b, 32-d group, T-half). 4 chunks per block.
// Per chunk: coalesced tile load to shared, then conflict-free class-ordered
// gather into register accumulators. NO atomics in the hot path.
// ---------------------------------------------------------------------------
__global__ void __launch_bounds__(THREADS)
cl_main_kernel(const float* __restrict__ feature) {
    const int bid  = blockIdx.x;
    const int ts   = bid % TSPLIT;
    const int dgrp = (bid / TSPLIT) % NDGRP;
    const int b    = bid / (TSPLIT * NDGRP);
    const int d0   = dgrp * DG;
    const int tid  = threadIdx.x;
    const int w    = tid >> 5;
    const int lane = tid & 31;

    __shared__ float          s_tile[DG * ST];     // 32 x 257 f32
    __shared__ unsigned short s_list[CHUNK];
    __shared__ unsigned short s_base[C_];
    __shared__ unsigned short s_cnt[C_];
    __shared__ float          s_red[THREADS / 32];

    float acc[8];
    #pragma unroll
    for (int i = 0; i < 8; i++) acc[i] = 0.0f;
    float sumsq = 0.0f;

    for (int ch = 0; ch < NCHUNKS_BLK; ch++) {
        const int tc = ts * NCHUNKS_BLK + ch;
        const int cu = b * NCHUNK_TOT + tc;

        s_list[tid] = g_list[cu * CHUNK + tid];
        if (tid < C_) {
            s_base[tid] = g_base[cu * C_ + tid];
            s_cnt [tid] = g_cnt [cu * C_ + tid];
        }

        // coalesced tile load: thread = t, unrolled over 32 d's (high MLP)
        const float* __restrict__ fb =
            feature + ((size_t)b * D_ + d0) * T_ + tc * CHUNK;
        #pragma unroll
        for (int dg = 0; dg < DG; dg++) {
            const float v = __ldg(&fb[dg * T_ + tid]);
            sumsq += v * v;
            s_tile[dg * ST + tid] = v;    // bank (dg+tid)%32: conflict-free
        }
        __syncthreads();

        // warp w handles classes {w, w+8, ..., w+56}; lane = d offset.
        #pragma unroll
        for (int ci = 0; ci < 8; ci++) {
            const int c    = w + 8 * ci;
            const int cnt  = s_cnt[c];
            const int base = s_base[c];
            float a = acc[ci];
            for (int k = 0; k < cnt; k++) {
                const int t = s_list[base + k];        // broadcast LDS
                a += s_tile[lane * ST + t];            // conflict-free LDS
            }
            acc[ci] = a;
        }
        __syncthreads();
    }

    // merge register accumulators -> global featsum (2048 REDG per block)
    #pragma unroll
    for (int ci = 0; ci < 8; ci++) {
        const int c = w + 8 * ci;
        atomicAdd(&g_featsum[c * D_ + d0 + lane], acc[ci]);
    }

    // block-reduce sumsq
    #pragma unroll
    for (int o = 16; o > 0; o >>= 1)
        sumsq += __shfl_down_sync(0xFFFFFFFFu, sumsq, o);
    if (lane == 0) s_red[w] = sumsq;
    __syncthreads();
    if (tid == 0) {
        float s = 0.0f;
        #pragma unroll
        for (int i = 0; i < THREADS / 32; i++) s += s_red[i];
        atomicAdd(&g_sumsq, s);
    }
}

// ---------------------------------------------------------------------------
// K3: finalize. Single block, 1024 threads.
//   counts[c]       = sum over chunks of g_cnt
//   difference[c,d] = cnt>0 ? centers - featsum/cnt : 0
//   loss            = (sumsq + sum_c cnt*||ctr||^2 - 2*sum ctr.featsum)/(N*D)
// out[0] = loss, out[1..8192] = difference row-major [C][D].
// ---------------------------------------------------------------------------
__global__ void __launch_bounds__(1024)
cl_finalize_kernel(const float* __restrict__ centers,
                   float* __restrict__ out) {
    __shared__ int   s_counts[C_];
    __shared__ float s_warp[32];

    const int tid = threadIdx.x;
    if (tid < C_) s_counts[tid] = 0;
    __syncthreads();

    // sum g_cnt[NCU_TOT][C_]: thread t covers class t&63, rows (t>>6)::16
    {
        const int c  = tid & (C_ - 1);
        const int r0 = tid >> 6;                 // 0..15
        int part = 0;
        for (int k = r0; k < NCU_TOT; k += 16)
            part += (int)g_cnt[k * C_ + c];
        atomicAdd(&s_counts[c], part);
    }
    __syncthreads();

    float local = 0.0f;
    for (int i = tid; i < C_ * D_; i += 1024) {
        const int   c   = i / D_;
        const float ctr = centers[i];
        const float fs  = g_featsum[i];
        const int   cnt = s_counts[c];
        out[1 + i] = (cnt > 0) ? (ctr - fs / (float)cnt) : 0.0f;
        local += (float)cnt * ctr * ctr - 2.0f * ctr * fs;
    }

    #pragma unroll
    for (int o = 16; o > 0; o >>= 1)
        local += __shfl_down_sync(0xFFFFFFFFu, local, o);
    if ((tid & 31) == 0) s_warp[tid >> 5] = local;
    __syncthreads();

    if (tid == 0) {
        float cross = 0.0f;
        #pragma unroll
        for (int i = 0; i < 32; i++) cross += s_warp[i];
        out[0] = (g_sumsq + cross) / (float)ND_;
    }
}

// ---------------------------------------------------------------------------
extern "C" void kernel_launch(void* const* d_in, const int* in_sizes, int n_in,
                              void* d_out, int out_size) {
    const float* feature = (const float*)d_in[0];
    const void*  label   = d_in[1];
    const float* centers = (const float*)d_in[2];
    float* out = (float*)d_out;

    cl_bucket_kernel<<<NCU_TOT, THREADS>>>(label);
    cl_main_kernel<<<B_ * NDGRP * TSPLIT, THREADS>>>(feature);
    cl_finalize_kernel<<<1, 1024>>>(centers, out);
}

// round 6
// speedup vs baseline: 1.9380x; 1.0614x over previous
#include <cuda_runtime.h>
#include <cstdint>

// Problem constants
#define B_  128
#define D_  128
#define T_  2048
#define C_  64
#define N_  (B_ * T_)                       // 262144
#define ND_ ((long long)N_ * D_)            // 33.5M

// Tiling
#define CHUNK       256
#define NCHUNK_TOT  (T_ / CHUNK)            // 8
#define NCHUNKS_BLK 4
#define TSPLIT      (NCHUNK_TOT / NCHUNKS_BLK)  // 2
#define DG          32
#define NDGRP       (D_ / DG)               // 4
#define ST          (CHUNK + 1)             // odd stride: conflict-free both ways
#define THREADS     256
#define NCU_TOT     (B_ * NCHUNK_TOT)       // 1024

// ---------------- device scratch (no allocations allowed) ----------------
__device__ float          g_featsum[C_ * D_];
__device__ int            g_counts[C_];
__device__ float          g_sumsq;
__device__ unsigned short g_list[NCU_TOT * CHUNK];
__device__ unsigned short g_base[NCU_TOT * C_];
__device__ unsigned short g_cnt [NCU_TOT * C_];

// ---------------------------------------------------------------------------
// K1: bucket t-indices by class per (b, chunk). Warp-scan prefix (no serial
// chain). Also zeroes g_featsum / g_counts / g_sumsq.
// ---------------------------------------------------------------------------
__global__ void __launch_bounds__(THREADS)
cl_bucket_kernel(const void* __restrict__ label_raw) {
    const int cu  = blockIdx.x;
    const int b   = cu / NCHUNK_TOT;
    const int tc  = cu % NCHUNK_TOT;
    const int tid = threadIdx.x;

    __shared__ int           s_cnt[C_];
    __shared__ int           s_off[C_];
    __shared__ int           s_lab64;
    __shared__ unsigned char s_lab[CHUNK];

    if (cu < (C_ * D_) / THREADS)
        g_featsum[cu * THREADS + tid] = 0.0f;
    if (cu == 0) {
        if (tid < C_) g_counts[tid] = 0;
        if (tid == 0) g_sumsq = 0.0f;
    }
    if (tid < C_) s_cnt[tid] = 0;

    // label dtype detect (int64 vs int32): first 64 words, always in-bounds
    if (tid == 0) {
        const long long* l = (const long long*)label_raw;
        int ok = 1;
        for (int i = 0; i < 64; i++) {
            long long v = l[i];
            if (v < 0 || v >= C_) { ok = 0; break; }
        }
        s_lab64 = ok;
    }
    __syncthreads();

    const int* __restrict__ lab32 = (const int*)label_raw;
    const int gi  = b * T_ + tc * CHUNK + tid;
    const int lab = s_lab64 ? lab32[2 * gi] : lab32[gi];
    s_lab[tid] = (unsigned char)lab;
    atomicAdd(&s_cnt[lab], 1);
    __syncthreads();

    // warp-scan exclusive prefix over 64 counters (lane i owns classes 2i,2i+1)
    if (tid < 32) {
        const int c0 = s_cnt[2 * tid];
        const int c1 = s_cnt[2 * tid + 1];
        int scan = c0 + c1;
        #pragma unroll
        for (int o = 1; o < 32; o <<= 1) {
            int v = __shfl_up_sync(0xFFFFFFFFu, scan, o);
            if (tid >= o) scan += v;
        }
        const int excl = scan - (c0 + c1);
        s_off[2 * tid]     = excl;
        s_off[2 * tid + 1] = excl + c0;
        g_base[cu * C_ + 2 * tid]     = (unsigned short)excl;
        g_base[cu * C_ + 2 * tid + 1] = (unsigned short)(excl + c0);
        g_cnt [cu * C_ + 2 * tid]     = (unsigned short)c0;
        g_cnt [cu * C_ + 2 * tid + 1] = (unsigned short)c1;
    }
    __syncthreads();

    const int pos = atomicAdd(&s_off[s_lab[tid]], 1);
    g_list[cu * CHUNK + pos] = (unsigned short)tid;
}

// ---------------------------------------------------------------------------
// K2: streaming pass, software-pipelined across chunks through registers.
// Per chunk: STS staged regs -> tile, prefetch next chunk (LDG overlaps
// gather), conflict-free class-ordered gather, zero atomics in hot path.
// ---------------------------------------------------------------------------
__global__ void __launch_bounds__(THREADS, 4)
cl_main_kernel(const float* __restrict__ feature) {
    const int bid  = blockIdx.x;
    const int ts   = bid % TSPLIT;
    const int dgrp = (bid / TSPLIT) % NDGRP;
    const int b    = bid / (TSPLIT * NDGRP);
    const int d0   = dgrp * DG;
    const int tid  = threadIdx.x;
    const int w    = tid >> 5;
    const int lane = tid & 31;

    __shared__ float          s_tile[DG * ST];
    __shared__ unsigned short s_list[CHUNK];
    __shared__ unsigned short s_base[C_];
    __shared__ unsigned short s_cnt[C_];
    __shared__ float          s_red[THREADS / 32];

    const float* __restrict__ fblk =
        feature + ((size_t)b * D_ + d0) * T_ + (size_t)ts * NCHUNKS_BLK * CHUNK;
    const int cu0 = b * NCHUNK_TOT + ts * NCHUNKS_BLK;

    float r[DG];
    unsigned short rlist = 0, rbase = 0, rcnt = 0;

    // prologue: prefetch chunk 0
    {
        const float* __restrict__ fb = fblk;
        #pragma unroll
        for (int dg = 0; dg < DG; dg++) r[dg] = __ldg(&fb[dg * T_ + tid]);
        rlist = g_list[cu0 * CHUNK + tid];
        if (tid < C_) {
            rbase = g_base[cu0 * C_ + tid];
            rcnt  = g_cnt [cu0 * C_ + tid];
        }
    }

    float acc[8];
    #pragma unroll
    for (int i = 0; i < 8; i++) acc[i] = 0.0f;
    float sumsq   = 0.0f;
    int   cnt_acc = 0;
    const bool do_cnt = (dgrp == 0);

    for (int ch = 0; ch < NCHUNKS_BLK; ch++) {
        if (ch) __syncthreads();            // tile free (prev gather done)

        // stage regs -> shared (conflict-free: stride-1 across lanes)
        #pragma unroll
        for (int dg = 0; dg < DG; dg++) {
            const float v = r[dg];
            sumsq += v * v;
            s_tile[dg * ST + tid] = v;
        }
        s_list[tid] = rlist;
        if (tid < C_) {
            s_base[tid] = rbase;
            s_cnt [tid] = rcnt;
            if (do_cnt) cnt_acc += (int)rcnt;
        }
        __syncthreads();                    // tile + lists ready

        // prefetch chunk ch+1 (independent of gather -> overlaps it)
        if (ch + 1 < NCHUNKS_BLK) {
            const float* __restrict__ fb = fblk + (ch + 1) * CHUNK;
            #pragma unroll
            for (int dg = 0; dg < DG; dg++) r[dg] = __ldg(&fb[dg * T_ + tid]);
            const int cu = cu0 + ch + 1;
            rlist = g_list[cu * CHUNK + tid];
            if (tid < C_) {
                rbase = g_base[cu * C_ + tid];
                rcnt  = g_cnt [cu * C_ + tid];
            }
        }

        // gather: warp w owns classes {w, w+8, ..., w+56}; lane = d offset
        #pragma unroll
        for (int ci = 0; ci < 8; ci++) {
            const int c    = w + 8 * ci;
            const int cnt  = s_cnt[c];
            const int base = s_base[c];
            float a = acc[ci];
            int k = 0;
            for (; k + 4 <= cnt; k += 4) {
                const int t0 = s_list[base + k + 0];
                const int t1 = s_list[base + k + 1];
                const int t2 = s_list[base + k + 2];
                const int t3 = s_list[base + k + 3];
                a += s_tile[lane * ST + t0];
                a += s_tile[lane * ST + t1];
                a += s_tile[lane * ST + t2];
                a += s_tile[lane * ST + t3];
            }
            for (; k < cnt; k++)
                a += s_tile[lane * ST + s_list[base + k]];
            acc[ci] = a;
        }
    }

    // merge register accumulators -> global featsum
    #pragma unroll
    for (int ci = 0; ci < 8; ci++) {
        const int c = w + 8 * ci;
        atomicAdd(&g_featsum[c * D_ + d0 + lane], acc[ci]);
    }

    if (do_cnt && tid < C_) atomicAdd(&g_counts[tid], cnt_acc);

    // block-reduce sumsq
    #pragma unroll
    for (int o = 16; o > 0; o >>= 1)
        sumsq += __shfl_down_sync(0xFFFFFFFFu, sumsq, o);
    if (lane == 0) s_red[w] = sumsq;
    __syncthreads();
    if (tid == 0) {
        float s = 0.0f;
        #pragma unroll
        for (int i = 0; i < THREADS / 32; i++) s += s_red[i];
        atomicAdd(&g_sumsq, s);
    }
}

// ---------------------------------------------------------------------------
// K3: finalize (single small block; counts already in g_counts).
//   difference[c,d] = cnt>0 ? centers - featsum/cnt : 0
//   loss = (sumsq + sum_c cnt*||ctr||^2 - 2*sum ctr.featsum) / (N*D)
// out[0] = loss, out[1..8192] = difference row-major [C][D].
// ---------------------------------------------------------------------------
__global__ void __launch_bounds__(1024)
cl_finalize_kernel(const float* __restrict__ centers,
                   float* __restrict__ out) {
    __shared__ float s_warp[32];
    const int tid = threadIdx.x;

    float local = 0.0f;
    #pragma unroll
    for (int i = tid; i < C_ * D_; i += 1024) {
        const int   c   = i >> 7;               // i / D_
        const float ctr = centers[i];
        const float fs  = g_featsum[i];
        const int   cnt = g_counts[c];
        out[1 + i] = (cnt > 0) ? (ctr - fs / (float)cnt) : 0.0f;
        local += (float)cnt * ctr * ctr - 2.0f * ctr * fs;
    }

    #pragma unroll
    for (int o = 16; o > 0; o >>= 1)
        local += __shfl_down_sync(0xFFFFFFFFu, local, o);
    if ((tid & 31) == 0) s_warp[tid >> 5] = local;
    __syncthreads();

    if (tid == 0) {
        float cross = 0.0f;
        #pragma unroll
        for (int i = 0; i < 32; i++) cross += s_warp[i];
        out[0] = (g_sumsq + cross) / (float)ND_;
    }
}

// ---------------------------------------------------------------------------
extern "C" void kernel_launch(void* const* d_in, const int* in_sizes, int n_in,
                              void* d_out, int out_size) {
    const float* feature = (const float*)d_in[0];
    const void*  label   = d_in[1];
    const float* centers = (const float*)d_in[2];
    float* out = (float*)d_out;

    cl_bucket_kernel<<<NCU_TOT, THREADS>>>(label);
    cl_main_kernel<<<B_ * NDGRP * TSPLIT, THREADS>>>(feature);
    cl_finalize_kernel<<<1, 1024>>>(centers, out);
}